// round 8
// baseline (speedup 1.0000x reference)
#include <cuda_runtime.h>
#include <cuda_fp16.h>
#include <math.h>
#include <stdint.h>

// Problem constants
#define BATCH 2
#define NB    9216          // H*W per batch (96*96)
#define NPIX  (BATCH * NB)  // 18432
#define CIN   384
#define C1    256
#define C2    128
#define MASK_THR 0.2f

// Scratch (device globals: no allocations allowed)
__device__ float  g_h1[(size_t)C1 * NPIX];     // [o][n]
__device__ float  g_feat[(size_t)NPIX * C2];   // [n][c]
__device__ float  g_rf[(size_t)NPIX * C2];     // [n][c] normalized fp32
__device__ __align__(256) __half g_hih[(size_t)NPIX * C2]; // fp16 hi part
__device__ __align__(256) __half g_loh[(size_t)NPIX * C2]; // fp16 residual
// per-third top-2 candidates: [third][row][slot]
#define JSPLIT 3
__device__ float  g_t2v[JSPLIT * NPIX * 2];
__device__ int    g_t2i[JSPLIT * NPIX * 2];

// ---------------------------------------------------------------------------
// PTX helpers (baseline ISA only — compute_103 safe)
// ---------------------------------------------------------------------------
__device__ __forceinline__ uint32_t smem_u32(const void* p) {
    return (uint32_t)__cvta_generic_to_shared(p);
}
#define CP16(dst, src) \
    asm volatile("cp.async.cg.shared.global [%0], [%1], 16;" :: "r"(dst), "l"(src))
#define CPCOMMIT() asm volatile("cp.async.commit_group;")
#define CPWAIT0()  asm volatile("cp.async.wait_group 0;" ::: "memory")

#define LDSM4(r0, r1, r2, r3, addr) \
    asm volatile("ldmatrix.sync.aligned.m8n8.x4.shared.b16 {%0,%1,%2,%3}, [%4];" \
        : "=r"(r0), "=r"(r1), "=r"(r2), "=r"(r3) : "r"(addr))

#define MMA16816(c, a, b) \
    asm volatile("mma.sync.aligned.m16n8k16.row.col.f32.f16.f16.f32 " \
        "{%0,%1,%2,%3}, {%4,%5,%6,%7}, {%8,%9}, {%0,%1,%2,%3};" \
        : "+f"((c)[0]), "+f"((c)[1]), "+f"((c)[2]), "+f"((c)[3]) \
        : "r"((a)[0]), "r"((a)[1]), "r"((a)[2]), "r"((a)[3]), \
          "r"((b)[0]), "r"((b)[1]))

// ---------------------------------------------------------------------------
// GEMM1: g_h1[o][n] = relu( sum_k W1[o][k] * X[b][k][hw] + b1[o] )
// ---------------------------------------------------------------------------
__global__ void gemm1_kernel(const float* __restrict__ X,
                             const float* __restrict__ W1,
                             const float* __restrict__ b1v) {
    __shared__ float Ws[64 * 16];
    __shared__ float Xs[16 * 64];
    const int t  = threadIdx.x;
    const int tx = t & 15, ty = t >> 4;
    const int n0 = blockIdx.x * 64;
    const int o0 = blockIdx.y * 64;
    const int b  = n0 / NB;
    const int hw0 = n0 % NB;
    const float* Xb = X + (size_t)b * CIN * NB;

    float acc[4][4];
#pragma unroll
    for (int i = 0; i < 4; i++)
#pragma unroll
        for (int j = 0; j < 4; j++) acc[i][j] = 0.f;

    const int lo = t >> 2, lq = t & 3;
    const int lk = t >> 4, ln4 = t & 15;

    for (int k0 = 0; k0 < CIN; k0 += 16) {
        float4 w = *(const float4*)&W1[(size_t)(o0 + lo) * CIN + k0 + lq * 4];
        *(float4*)&Ws[lo * 16 + lq * 4] = w;
        float4 x = *(const float4*)&Xb[(size_t)(k0 + lk) * NB + hw0 + ln4 * 4];
        *(float4*)&Xs[lk * 64 + ln4 * 4] = x;
        __syncthreads();
#pragma unroll
        for (int k4 = 0; k4 < 4; k4++) {
            float4 w0 = *(const float4*)&Ws[(ty * 4 + 0) * 16 + k4 * 4];
            float4 w1 = *(const float4*)&Ws[(ty * 4 + 1) * 16 + k4 * 4];
            float4 w2 = *(const float4*)&Ws[(ty * 4 + 2) * 16 + k4 * 4];
            float4 w3 = *(const float4*)&Ws[(ty * 4 + 3) * 16 + k4 * 4];
            const float* wp0 = (const float*)&w0;
            const float* wp1 = (const float*)&w1;
            const float* wp2 = (const float*)&w2;
            const float* wp3 = (const float*)&w3;
#pragma unroll
            for (int kk = 0; kk < 4; kk++) {
                float4 xv = *(const float4*)&Xs[(k4 * 4 + kk) * 64 + tx * 4];
                float a0 = wp0[kk], a1 = wp1[kk], a2 = wp2[kk], a3 = wp3[kk];
                acc[0][0] += a0 * xv.x; acc[0][1] += a0 * xv.y; acc[0][2] += a0 * xv.z; acc[0][3] += a0 * xv.w;
                acc[1][0] += a1 * xv.x; acc[1][1] += a1 * xv.y; acc[1][2] += a1 * xv.z; acc[1][3] += a1 * xv.w;
                acc[2][0] += a2 * xv.x; acc[2][1] += a2 * xv.y; acc[2][2] += a2 * xv.z; acc[2][3] += a2 * xv.w;
                acc[3][0] += a3 * xv.x; acc[3][1] += a3 * xv.y; acc[3][2] += a3 * xv.z; acc[3][3] += a3 * xv.w;
            }
        }
        __syncthreads();
    }
#pragma unroll
    for (int i = 0; i < 4; i++) {
        int o = o0 + ty * 4 + i;
        float bias = b1v[o];
        float4 r;
        r.x = fmaxf(acc[i][0] + bias, 0.f);
        r.y = fmaxf(acc[i][1] + bias, 0.f);
        r.z = fmaxf(acc[i][2] + bias, 0.f);
        r.w = fmaxf(acc[i][3] + bias, 0.f);
        *(float4*)&g_h1[(size_t)o * NPIX + n0 + tx * 4] = r;
    }
}

// ---------------------------------------------------------------------------
// GEMM2: g_feat[n][o] = sum_k W2[o][k] * g_h1[k][n] + b2[o]
// ---------------------------------------------------------------------------
__global__ void gemm2_kernel(const float* __restrict__ W2,
                             const float* __restrict__ b2v) {
    __shared__ float Ws[64 * 16];
    __shared__ float Hs[16 * 64];
    const int t  = threadIdx.x;
    const int tx = t & 15, ty = t >> 4;
    const int n0 = blockIdx.x * 64;
    const int o0 = blockIdx.y * 64;

    float acc[4][4];
#pragma unroll
    for (int i = 0; i < 4; i++)
#pragma unroll
        for (int j = 0; j < 4; j++) acc[i][j] = 0.f;

    const int lo = t >> 2, lq = t & 3;
    const int lk = t >> 4, ln4 = t & 15;

    for (int k0 = 0; k0 < C1; k0 += 16) {
        float4 w = *(const float4*)&W2[(size_t)(o0 + lo) * C1 + k0 + lq * 4];
        *(float4*)&Ws[lo * 16 + lq * 4] = w;
        float4 h = *(const float4*)&g_h1[(size_t)(k0 + lk) * NPIX + n0 + ln4 * 4];
        *(float4*)&Hs[lk * 64 + ln4 * 4] = h;
        __syncthreads();
#pragma unroll
        for (int k4 = 0; k4 < 4; k4++) {
            float4 w0 = *(const float4*)&Ws[(ty * 4 + 0) * 16 + k4 * 4];
            float4 w1 = *(const float4*)&Ws[(ty * 4 + 1) * 16 + k4 * 4];
            float4 w2 = *(const float4*)&Ws[(ty * 4 + 2) * 16 + k4 * 4];
            float4 w3 = *(const float4*)&Ws[(ty * 4 + 3) * 16 + k4 * 4];
            const float* wp0 = (const float*)&w0;
            const float* wp1 = (const float*)&w1;
            const float* wp2 = (const float*)&w2;
            const float* wp3 = (const float*)&w3;
#pragma unroll
            for (int kk = 0; kk < 4; kk++) {
                float4 xv = *(const float4*)&Hs[(k4 * 4 + kk) * 64 + tx * 4];
                float a0 = wp0[kk], a1 = wp1[kk], a2 = wp2[kk], a3 = wp3[kk];
                acc[0][0] += a0 * xv.x; acc[0][1] += a0 * xv.y; acc[0][2] += a0 * xv.z; acc[0][3] += a0 * xv.w;
                acc[1][0] += a1 * xv.x; acc[1][1] += a1 * xv.y; acc[1][2] += a1 * xv.z; acc[1][3] += a1 * xv.w;
                acc[2][0] += a2 * xv.x; acc[2][1] += a2 * xv.y; acc[2][2] += a2 * xv.z; acc[2][3] += a2 * xv.w;
                acc[3][0] += a3 * xv.x; acc[3][1] += a3 * xv.y; acc[3][2] += a3 * xv.z; acc[3][3] += a3 * xv.w;
            }
        }
        __syncthreads();
    }
    float bias[4];
#pragma unroll
    for (int i = 0; i < 4; i++) bias[i] = b2v[o0 + ty * 4 + i];
#pragma unroll
    for (int j = 0; j < 4; j++) {
        int n = n0 + tx * 4 + j;
        float4 r;
        r.x = acc[0][j] + bias[0];
        r.y = acc[1][j] + bias[1];
        r.z = acc[2][j] + bias[2];
        r.w = acc[3][j] + bias[3];
        *(float4*)&g_feat[(size_t)n * C2 + o0 + ty * 4] = r;
    }
}

// ---------------------------------------------------------------------------
// Normalize: rf = feat / max(||feat||, 1e-12); fp32 rf + fp16 hi/lo split.
// ---------------------------------------------------------------------------
__global__ void normalize_kernel() {
    const int n = blockIdx.x;
    const int c = threadIdx.x;
    float v = g_feat[(size_t)n * C2 + c];
    float s = v * v;
#pragma unroll
    for (int off = 16; off; off >>= 1) s += __shfl_xor_sync(0xffffffffu, s, off);
    __shared__ float ws[4];
    if ((c & 31) == 0) ws[c >> 5] = s;
    __syncthreads();
    float tot = ws[0] + ws[1] + ws[2] + ws[3];
    float norm = sqrtf(tot);
    float nf = v / fmaxf(norm, 1e-12f);
    g_rf[(size_t)n * C2 + c] = nf;
    __half hi = __float2half_rn(nf);
    g_hih[(size_t)n * C2 + c] = hi;
    g_loh[(size_t)n * C2 + c] = __float2half_rn(nf - __half2float(hi));
}

// ---------------------------------------------------------------------------
// Top-2 insert with jax top_k tie-breaking (equal value -> lower index).
// ---------------------------------------------------------------------------
__device__ __forceinline__ void ins2(float v, int j,
                                     float& v1, int& i1, float& v2, int& i2) {
    if (v > v1 || (v == v1 && j < i1)) {
        v2 = v1; i2 = i1; v1 = v; i1 = j;
    } else if (v > v2 || (v == v2 && j < i2)) {
        v2 = v; i2 = j;
    }
}

// ---------------------------------------------------------------------------
// Tensor-core (mma.sync fp16 3-term) similarity + top-2, 3-CTA/SM version.
// Grid: (72 i-tiles, 3 j-thirds, 2 batches) = 432 CTAs -> 3 CTAs/SM
// (24 warps/SM). JT=32 so smem/CTA = A-lo 32KB + B dbuf 2x16KB = 64KB;
// __launch_bounds__(256,3) forces regs<=85 (acc 16 + a_hi 32 + bf 8 + al 4).
// Per k-step: al<-smem; bh 2xLDSM -> 4 MMA; al x bh 4 MMA; bl -> 4 MMA.
// D = Ah*Bh' + Al*Bh' + Ah*Bl'  (fp32 accum) — error ~3e-7.
// Per-third top-2 candidates to global; merged in dist kernel.
// ---------------------------------------------------------------------------
#define JT    32
#define JCH   (NB / JSPLIT)        // 3072
#define NTJ3  (JCH / JT)           // 96
#define ALO_BYTES 32768            // A-lo resident: 128 rows x 256B
#define BUFB  16384                // one B buffer: hi 8KB + lo 8KB
#define SIM_SMEM (ALO_BYTES + 2 * BUFB)   // 64KB

__device__ __forceinline__ uint32_t sw_off(int r, int c) {
    // row r (256B rows), 16B chunk c, XOR swizzle on chunk index
    return (uint32_t)(r * 256 + ((c ^ (r & 7)) << 4));
}

__global__ void __launch_bounds__(256, 3) sim_mma_kernel() {
    extern __shared__ __align__(1024) char sm[];
    const int t = threadIdx.x;
    const int w = t >> 5, l = t & 31;
    const int jh = blockIdx.y;
    const int b  = blockIdx.z;
    const int i0 = blockIdx.x * 128;
    const int jbase = jh * JCH;
    const __half* Hsrc = g_hih + (size_t)b * NB * C2;
    const __half* Lsrc = g_loh + (size_t)b * NB * C2;
    const uint32_t sbA = smem_u32(sm);          // A-lo resident region
    const uint32_t bb0 = sbA + ALO_BYTES;       // B buffers (2 x 16KB)

    // ---- Stage A-lo (resident) + A-hi (temporarily in B region, 32KB) ----
#pragma unroll
    for (int e = 0; e < 8; e++) {
        int id = e * 256 + t;          // 0..2047 : 128 rows x 16 chunks
        int r = id >> 4, c = id & 15;
        uint32_t o = sw_off(r, c);
        CP16(sbA + o, (const char*)(Lsrc + (size_t)(i0 + r) * C2) + c * 16);
        CP16(bb0 + o, (const char*)(Hsrc + (size_t)(i0 + r) * C2) + c * 16);
    }
    CPCOMMIT(); CPWAIT0();
    __syncthreads();

    // ---- A-hi fragments (register resident): a_hi[ks][4] ----
    const int sub = l >> 3;
    const int arl = ((sub & 1) << 3) + (l & 7);
    const int cb  = sub >> 1;
    const int ar  = w * 16 + arl;
    uint32_t a_hi[8][4];
#pragma unroll
    for (int ks = 0; ks < 8; ks++) {
        uint32_t ad = bb0 + sw_off(ar, ks * 2 + cb);
        LDSM4(a_hi[ks][0], a_hi[ks][1], a_hi[ks][2], a_hi[ks][3], ad);
    }
    __syncthreads();   // B region free for streaming now

    // B-tile ldmatrix address pieces (per thread)
    const int brn = ((sub >> 1) << 3) + (l & 7);   // row within 16-row group
    const int bcb = sub & 1;                       // k-chunk select

    // ---- prefetch B tile 0 into buffer 0 (32 rows x 16 chunks = 512) ----
#pragma unroll
    for (int e = 0; e < 2; e++) {
        int id = e * 256 + t;      // 0..511
        int r = id >> 4, c = id & 15;
        uint32_t o = sw_off(r, c);
        CP16(bb0 + o,        (const char*)(Hsrc + (size_t)(jbase + r) * C2) + c * 16);
        CP16(bb0 + 8192 + o, (const char*)(Lsrc + (size_t)(jbase + r) * C2) + c * 16);
    }
    CPCOMMIT();

    // per-thread running top-2 for two rows: row_a = w*16 + l/4, row_b = +8
    float v1a = -INFINITY, v2a = -INFINITY, v1b = -INFINITY, v2b = -INFINITY;
    int   i1a = 0x7fffffff, i2a = 0x7fffffff, i1b = 0x7fffffff, i2b = 0x7fffffff;

    for (int jt = 0; jt < NTJ3; jt++) {
        CPWAIT0();
        __syncthreads();

        // prefetch next tile into other buffer (overlaps compute)
        if (jt + 1 < NTJ3) {
            const int j0n = jbase + (jt + 1) * JT;
            const uint32_t bo = bb0 + (uint32_t)((jt + 1) & 1) * BUFB;
#pragma unroll
            for (int e = 0; e < 2; e++) {
                int id = e * 256 + t;
                int r = id >> 4, c = id & 15;
                uint32_t o = bo + sw_off(r, c);
                CP16(o,        (const char*)(Hsrc + (size_t)(j0n + r) * C2) + c * 16);
                CP16(o + 8192, (const char*)(Lsrc + (size_t)(j0n + r) * C2) + c * 16);
            }
            CPCOMMIT();
        }

        const uint32_t bo = bb0 + (uint32_t)(jt & 1) * BUFB;
        float acc[4][4];
#pragma unroll
        for (int nf = 0; nf < 4; nf++)
#pragma unroll
            for (int q = 0; q < 4; q++) acc[nf][q] = 0.f;

#pragma unroll
        for (int ks = 0; ks < 8; ks++) {
            const int ck = ks * 2;
            // stream A-lo fragment for this k-step
            uint32_t al[4];
            LDSM4(al[0], al[1], al[2], al[3], sbA + sw_off(ar, ck + cb));
            // load both B-hi fragments (8 regs)
            uint32_t bf[8];
#pragma unroll
            for (int nb = 0; nb < 2; nb++) {
                uint32_t ad = bo + sw_off(nb * 16 + brn, ck + bcb);
                LDSM4(bf[4 * nb], bf[4 * nb + 1], bf[4 * nb + 2], bf[4 * nb + 3], ad);
            }
#pragma unroll
            for (int nf = 0; nf < 4; nf++) MMA16816(acc[nf], a_hi[ks], bf + 2 * nf);
#pragma unroll
            for (int nf = 0; nf < 4; nf++) MMA16816(acc[nf], al, bf + 2 * nf);
            // reload same regs with B-lo fragments
#pragma unroll
            for (int nb = 0; nb < 2; nb++) {
                uint32_t ad = bo + 8192 + sw_off(nb * 16 + brn, ck + bcb);
                LDSM4(bf[4 * nb], bf[4 * nb + 1], bf[4 * nb + 2], bf[4 * nb + 3], ad);
            }
#pragma unroll
            for (int nf = 0; nf < 4; nf++) MMA16816(acc[nf], a_hi[ks], bf + 2 * nf);
        }

        // ---- fold tile into running top-2 (guarded by max-tree) ----
        const int cbase = jbase + jt * JT + (l & 3) * 2;
        float mA = fmaxf(acc[0][0], acc[0][1]);
        float mB = fmaxf(acc[0][2], acc[0][3]);
#pragma unroll
        for (int nf = 1; nf < 4; nf++) {
            mA = fmaxf(mA, fmaxf(acc[nf][0], acc[nf][1]));
            mB = fmaxf(mB, fmaxf(acc[nf][2], acc[nf][3]));
        }
        if (mA >= v2a) {
#pragma unroll
            for (int nf = 0; nf < 4; nf++) {
                ins2(acc[nf][0], cbase + nf * 8,     v1a, i1a, v2a, i2a);
                ins2(acc[nf][1], cbase + nf * 8 + 1, v1a, i1a, v2a, i2a);
            }
        }
        if (mB >= v2b) {
#pragma unroll
            for (int nf = 0; nf < 4; nf++) {
                ins2(acc[nf][2], cbase + nf * 8,     v1b, i1b, v2b, i2b);
                ins2(acc[nf][3], cbase + nf * 8 + 1, v1b, i1b, v2b, i2b);
            }
        }
    }

    // ---- merge across the 4 lanes (l&3) sharing each row ----
#pragma unroll
    for (int off = 1; off <= 2; off <<= 1) {
        float ov1 = __shfl_xor_sync(0xffffffffu, v1a, off);
        int   oi1 = __shfl_xor_sync(0xffffffffu, i1a, off);
        float ov2 = __shfl_xor_sync(0xffffffffu, v2a, off);
        int   oi2 = __shfl_xor_sync(0xffffffffu, i2a, off);
        ins2(ov1, oi1, v1a, i1a, v2a, i2a);
        ins2(ov2, oi2, v1a, i1a, v2a, i2a);
        ov1 = __shfl_xor_sync(0xffffffffu, v1b, off);
        oi1 = __shfl_xor_sync(0xffffffffu, i1b, off);
        ov2 = __shfl_xor_sync(0xffffffffu, v2b, off);
        oi2 = __shfl_xor_sync(0xffffffffu, i2b, off);
        ins2(ov1, oi1, v1b, i1b, v2b, i2b);
        ins2(ov2, oi2, v1b, i1b, v2b, i2b);
    }
    if ((l & 3) == 0) {
        const int rowa = b * NB + i0 + w * 16 + (l >> 2);
        const int rowb = rowa + 8;
        const size_t pa = ((size_t)jh * NPIX + rowa) * 2;
        const size_t pb = ((size_t)jh * NPIX + rowb) * 2;
        g_t2v[pa]     = v1a; g_t2i[pa]     = i1a;
        g_t2v[pa + 1] = v2a; g_t2i[pa + 1] = i2a;
        g_t2v[pb]     = v1b; g_t2i[pb]     = i1b;
        g_t2v[pb + 1] = v2b; g_t2i[pb + 1] = i2b;
    }
}

// ---------------------------------------------------------------------------
// Merge j-thirds + distance + mask (exact fp32 recompute, matches reference).
// ---------------------------------------------------------------------------
__global__ void dist_kernel(float* __restrict__ out) {
    const int gw   = (int)((blockIdx.x * blockDim.x + threadIdx.x) >> 5);
    const int lane = threadIdx.x & 31;
    if (gw >= NPIX) return;
    const int b = gw / NB;
    int nn = 0;
    if (lane == 0) {
        float v1 = -INFINITY, v2 = -INFINITY;
        int   i1 = 0x7fffffff, i2 = 0x7fffffff;
#pragma unroll
        for (int h = 0; h < JSPLIT; h++) {
            const size_t p = ((size_t)h * NPIX + gw) * 2;
            ins2(g_t2v[p],     g_t2i[p],     v1, i1, v2, i2);
            ins2(g_t2v[p + 1], g_t2i[p + 1], v1, i1, v2, i2);
        }
        nn = i2;
    }
    nn = __shfl_sync(0xffffffffu, nn, 0);
    const float* a = g_rf + (size_t)gw * C2;
    const float* c = g_rf + (size_t)(b * NB + nn) * C2;
    float4 av = *(const float4*)&a[lane * 4];
    float4 cv = *(const float4*)&c[lane * 4];
    float dx = av.x - cv.x, dy = av.y - cv.y, dz = av.z - cv.z, dw = av.w - cv.w;
    float s = dx * dx + dy * dy + dz * dz + dw * dw;
#pragma unroll
    for (int off = 16; off; off >>= 1) s += __shfl_xor_sync(0xffffffffu, s, off);
    if (lane == 0) {
        float d = sqrtf(s);
        out[NPIX + gw] = d;
        out[gw] = (d > MASK_THR) ? 1.0f : 0.0f;
    }
}

// ---------------------------------------------------------------------------
extern "C" void kernel_launch(void* const* d_in, const int* in_sizes, int n_in,
                              void* d_out, int out_size) {
    const float* features = (const float*)d_in[0];
    const float* W1 = (const float*)d_in[1];
    const float* b1 = (const float*)d_in[2];
    const float* W2 = (const float*)d_in[3];
    const float* b2 = (const float*)d_in[4];
    float* out = (float*)d_out;

    cudaFuncSetAttribute(sim_mma_kernel,
                         cudaFuncAttributeMaxDynamicSharedMemorySize, SIM_SMEM);

    gemm1_kernel<<<dim3(NPIX / 64, C1 / 64), 256>>>(features, W1, b1);
    gemm2_kernel<<<dim3(NPIX / 64, C2 / 64), 256>>>(W2, b2);
    normalize_kernel<<<NPIX, 128>>>();
    sim_mma_kernel<<<dim3(NB / 128, JSPLIT, BATCH), 256, SIM_SMEM>>>();
    dist_kernel<<<(NPIX * 32 + 255) / 256, 256>>>(out);
}

// round 9
// speedup vs baseline: 1.2295x; 1.2295x over previous
#include <cuda_runtime.h>
#include <cuda_fp16.h>
#include <math.h>
#include <stdint.h>

// Problem constants
#define BATCH 2
#define NB    9216          // H*W per batch (96*96)
#define NPIX  (BATCH * NB)  // 18432
#define CIN   384
#define C1    256
#define C2    128
#define MASK_THR 0.2f
#define JSPLIT 2

// Scratch (device globals: no allocations allowed)
__device__ __align__(256) __half g_xth[(size_t)NPIX * CIN]; // X^T hi [bp][c]
__device__ __align__(256) __half g_xtl[(size_t)NPIX * CIN]; // X^T lo
__device__ __align__(256) __half g_w1h[(size_t)C1 * CIN];
__device__ __align__(256) __half g_w1l[(size_t)C1 * CIN];
__device__ __align__(256) __half g_w2h[(size_t)C2 * C1];
__device__ __align__(256) __half g_w2l[(size_t)C2 * C1];
__device__ __align__(256) __half g_h1h[(size_t)NPIX * C1];  // relu(h1) hi
__device__ __align__(256) __half g_h1l[(size_t)NPIX * C1];  // relu(h1) lo
__device__ float  g_feat[(size_t)NPIX * C2];   // [n][c]
__device__ float  g_rf[(size_t)NPIX * C2];     // [n][c] normalized fp32
__device__ __align__(256) __half g_hih[(size_t)NPIX * C2]; // rf fp16 hi
__device__ __align__(256) __half g_loh[(size_t)NPIX * C2]; // rf fp16 residual
__device__ float  g_t2v[JSPLIT * NPIX * 2];
__device__ int    g_t2i[JSPLIT * NPIX * 2];

// ---------------------------------------------------------------------------
// PTX helpers (baseline ISA only — compute_103 safe)
// ---------------------------------------------------------------------------
__device__ __forceinline__ uint32_t smem_u32(const void* p) {
    return (uint32_t)__cvta_generic_to_shared(p);
}
#define CP16(dst, src) \
    asm volatile("cp.async.cg.shared.global [%0], [%1], 16;" :: "r"(dst), "l"(src))
#define CPCOMMIT() asm volatile("cp.async.commit_group;")
#define CPWAIT0()  asm volatile("cp.async.wait_group 0;" ::: "memory")

#define LDSM4(r0, r1, r2, r3, addr) \
    asm volatile("ldmatrix.sync.aligned.m8n8.x4.shared.b16 {%0,%1,%2,%3}, [%4];" \
        : "=r"(r0), "=r"(r1), "=r"(r2), "=r"(r3) : "r"(addr))

#define MMA16816(c, a, b) \
    asm volatile("mma.sync.aligned.m16n8k16.row.col.f32.f16.f16.f32 " \
        "{%0,%1,%2,%3}, {%4,%5,%6,%7}, {%8,%9}, {%0,%1,%2,%3};" \
        : "+f"((c)[0]), "+f"((c)[1]), "+f"((c)[2]), "+f"((c)[3]) \
        : "r"((a)[0]), "r"((a)[1]), "r"((a)[2]), "r"((a)[3]), \
          "r"((b)[0]), "r"((b)[1]))

// swizzle for 256B rows (sim kernel), 16B chunk c in 0..15
__device__ __forceinline__ uint32_t sw_off(int r, int c) {
    return (uint32_t)(r * 256 + ((c ^ (r & 7)) << 4));
}
// swizzle for 128B rows (MLP gemms), 16B chunk c in 0..7
__device__ __forceinline__ uint32_t sw128(int r, int c) {
    return (uint32_t)(r * 128 + ((c ^ (r & 7)) << 4));
}

// ---------------------------------------------------------------------------
// Prep: split W1/W2 into fp16 hi/lo
// ---------------------------------------------------------------------------
__global__ void splitw_kernel(const float* __restrict__ W1,
                              const float* __restrict__ W2) {
    int i = blockIdx.x * 256 + threadIdx.x;
    if (i < C1 * CIN) {
        float v = W1[i];
        __half h = __float2half_rn(v);
        g_w1h[i] = h;
        g_w1l[i] = __float2half_rn(v - __half2float(h));
    } else {
        int j = i - C1 * CIN;
        if (j < C2 * C1) {
            float v = W2[j];
            __half h = __float2half_rn(v);
            g_w2h[j] = h;
            g_w2l[j] = __float2half_rn(v - __half2float(h));
        }
    }
}

// ---------------------------------------------------------------------------
// Prep: transpose X [b][c][hw] -> Xt [b][hw][c], split fp16 hi/lo
// ---------------------------------------------------------------------------
__global__ void transpose_split_kernel(const float* __restrict__ X) {
    __shared__ float s[32][33];
    const int b = blockIdx.z;
    const int hw0 = blockIdx.x * 32;
    const int c0 = blockIdx.y * 32;
    const int tx = threadIdx.x, ty = threadIdx.y;
    const float* Xb = X + ((size_t)b * CIN + c0) * NB + hw0;
#pragma unroll
    for (int i = 0; i < 4; i++) {
        int cl = ty + 8 * i;
        s[cl][tx] = Xb[(size_t)cl * NB + tx];
    }
    __syncthreads();
#pragma unroll
    for (int i = 0; i < 4; i++) {
        int hwl = ty + 8 * i;
        float v = s[tx][hwl];
        __half h = __float2half_rn(v);
        size_t o = ((size_t)b * NB + hw0 + hwl) * CIN + c0 + tx;
        g_xth[o] = h;
        g_xtl[o] = __float2half_rn(v - __half2float(h));
    }
}

// ---------------------------------------------------------------------------
// Tensor-core MLP GEMM (shared machinery):
// D[m][n] = sum_k A[m][k] * B[n][k], 3-term fp16 hi/lo (error ~2^-22).
// CTA: m-tile 128, n-tile 64, K in 64-chunks double-buffered via cp.async.
// Smem: A 2 x (hi 16KB + lo 16KB) @0, B 2 x (hi 8KB + lo 8KB) @64KB = 96KB.
// ---------------------------------------------------------------------------
#define MLP_SMEM 98304

__device__ __forceinline__ void mlp_stage(uint32_t sb, int buf,
                                          const __half* __restrict__ Ah,
                                          const __half* __restrict__ Al,
                                          const __half* __restrict__ Bh,
                                          const __half* __restrict__ Bl,
                                          int m0, int n0, int kc0, int K, int t) {
    const uint32_t sA = sb + (uint32_t)buf * 32768u;
    const uint32_t sB = sb + 65536u + (uint32_t)buf * 16384u;
#pragma unroll
    for (int e = 0; e < 4; e++) {
        int id = e * 256 + t;          // 0..1023 : 128 rows x 8 chunks
        int r = id >> 3, c = id & 7;
        uint32_t o = sw128(r, c);
        const size_t off = (size_t)(m0 + r) * K + kc0 + c * 8;
        CP16(sA + o,          Ah + off);
        CP16(sA + 16384u + o, Al + off);
    }
#pragma unroll
    for (int e = 0; e < 2; e++) {
        int id = e * 256 + t;          // 0..511 : 64 rows x 8 chunks
        int r = id >> 3, c = id & 7;
        uint32_t o = sw128(r, c);
        const size_t off = (size_t)(n0 + r) * K + kc0 + c * 8;
        CP16(sB + o,         Bh + off);
        CP16(sB + 8192u + o, Bl + off);
    }
}

// K-loop body: fills acc[8][4]. Returns nothing; acc accumulated in caller regs.
#define MLP_COMPUTE_CHUNK(aB, bB)                                              \
    _Pragma("unroll")                                                          \
    for (int ks = 0; ks < 4; ks++) {                                           \
        const int ck = ks * 2;                                                 \
        uint32_t ah[4], al[4];                                                 \
        LDSM4(ah[0], ah[1], ah[2], ah[3], (aB) + sw128(ar, ck + cb));          \
        LDSM4(al[0], al[1], al[2], al[3], (aB) + 16384u + sw128(ar, ck + cb)); \
        uint32_t bf[16];                                                       \
        _Pragma("unroll")                                                      \
        for (int nb = 0; nb < 4; nb++) {                                       \
            uint32_t ad = (bB) + sw128(nb * 16 + brn, ck + bcb);               \
            LDSM4(bf[4*nb], bf[4*nb+1], bf[4*nb+2], bf[4*nb+3], ad);           \
        }                                                                      \
        _Pragma("unroll")                                                      \
        for (int nf = 0; nf < 8; nf++) MMA16816(acc[nf], ah, bf + 2 * nf);     \
        _Pragma("unroll")                                                      \
        for (int nf = 0; nf < 8; nf++) MMA16816(acc[nf], al, bf + 2 * nf);     \
        _Pragma("unroll")                                                      \
        for (int nb = 0; nb < 4; nb++) {                                       \
            uint32_t ad = (bB) + 8192u + sw128(nb * 16 + brn, ck + bcb);       \
            LDSM4(bf[4*nb], bf[4*nb+1], bf[4*nb+2], bf[4*nb+3], ad);           \
        }                                                                      \
        _Pragma("unroll")                                                      \
        for (int nf = 0; nf < 8; nf++) MMA16816(acc[nf], ah, bf + 2 * nf);     \
    }

// GEMM1: h1 = relu(Xt @ W1^T + b1), output split to fp16 hi/lo [pixel][256]
__global__ void __launch_bounds__(256, 2) gemm1_mma_kernel(const float* __restrict__ b1v) {
    extern __shared__ __align__(1024) char sm[];
    const int t = threadIdx.x, w = t >> 5, l = t & 31;
    const int m0 = blockIdx.x * 128, n0 = blockIdx.y * 64;
    const uint32_t sb = smem_u32(sm);
    const int sub = l >> 3;
    const int ar  = w * 16 + ((sub & 1) << 3) + (l & 7);
    const int cb  = sub >> 1;
    const int brn = ((sub >> 1) << 3) + (l & 7);
    const int bcb = sub & 1;

    mlp_stage(sb, 0, g_xth, g_xtl, g_w1h, g_w1l, m0, n0, 0, CIN, t);
    CPCOMMIT();

    float acc[8][4];
#pragma unroll
    for (int nf = 0; nf < 8; nf++)
#pragma unroll
        for (int q = 0; q < 4; q++) acc[nf][q] = 0.f;

    const int NCH = CIN / 64;   // 6
    for (int kc = 0; kc < NCH; kc++) {
        CPWAIT0();
        __syncthreads();
        if (kc + 1 < NCH) {
            mlp_stage(sb, (kc + 1) & 1, g_xth, g_xtl, g_w1h, g_w1l,
                      m0, n0, (kc + 1) * 64, CIN, t);
            CPCOMMIT();
        }
        const uint32_t aB = sb + (uint32_t)(kc & 1) * 32768u;
        const uint32_t bB = sb + 65536u + (uint32_t)(kc & 1) * 16384u;
        MLP_COMPUTE_CHUNK(aB, bB)
        __syncthreads();
    }

    const int rowa = m0 + w * 16 + (l >> 2);
#pragma unroll
    for (int nf = 0; nf < 8; nf++) {
        int col = n0 + nf * 8 + (l & 3) * 2;
        float b0 = b1v[col], b1 = b1v[col + 1];
        float v0 = fmaxf(acc[nf][0] + b0, 0.f);
        float v1 = fmaxf(acc[nf][1] + b1, 0.f);
        float v2 = fmaxf(acc[nf][2] + b0, 0.f);
        float v3 = fmaxf(acc[nf][3] + b1, 0.f);
        __half h0 = __float2half_rn(v0), h1 = __float2half_rn(v1);
        __half h2 = __float2half_rn(v2), h3 = __float2half_rn(v3);
        *(__half2*)&g_h1h[(size_t)rowa * C1 + col] = __halves2half2(h0, h1);
        *(__half2*)&g_h1l[(size_t)rowa * C1 + col] = __halves2half2(
            __float2half_rn(v0 - __half2float(h0)),
            __float2half_rn(v1 - __half2float(h1)));
        *(__half2*)&g_h1h[(size_t)(rowa + 8) * C1 + col] = __halves2half2(h2, h3);
        *(__half2*)&g_h1l[(size_t)(rowa + 8) * C1 + col] = __halves2half2(
            __float2half_rn(v2 - __half2float(h2)),
            __float2half_rn(v3 - __half2float(h3)));
    }
}

// GEMM2: feat = h1 @ W2^T + b2, output fp32 [pixel][128]
__global__ void __launch_bounds__(256, 2) gemm2_mma_kernel(const float* __restrict__ b2v) {
    extern __shared__ __align__(1024) char sm[];
    const int t = threadIdx.x, w = t >> 5, l = t & 31;
    const int m0 = blockIdx.x * 128, n0 = blockIdx.y * 64;
    const uint32_t sb = smem_u32(sm);
    const int sub = l >> 3;
    const int ar  = w * 16 + ((sub & 1) << 3) + (l & 7);
    const int cb  = sub >> 1;
    const int brn = ((sub >> 1) << 3) + (l & 7);
    const int bcb = sub & 1;

    mlp_stage(sb, 0, g_h1h, g_h1l, g_w2h, g_w2l, m0, n0, 0, C1, t);
    CPCOMMIT();

    float acc[8][4];
#pragma unroll
    for (int nf = 0; nf < 8; nf++)
#pragma unroll
        for (int q = 0; q < 4; q++) acc[nf][q] = 0.f;

    const int NCH = C1 / 64;    // 4
    for (int kc = 0; kc < NCH; kc++) {
        CPWAIT0();
        __syncthreads();
        if (kc + 1 < NCH) {
            mlp_stage(sb, (kc + 1) & 1, g_h1h, g_h1l, g_w2h, g_w2l,
                      m0, n0, (kc + 1) * 64, C1, t);
            CPCOMMIT();
        }
        const uint32_t aB = sb + (uint32_t)(kc & 1) * 32768u;
        const uint32_t bB = sb + 65536u + (uint32_t)(kc & 1) * 16384u;
        MLP_COMPUTE_CHUNK(aB, bB)
        __syncthreads();
    }

    const int rowa = m0 + w * 16 + (l >> 2);
#pragma unroll
    for (int nf = 0; nf < 8; nf++) {
        int col = n0 + nf * 8 + (l & 3) * 2;
        float b0 = b2v[col], b1 = b2v[col + 1];
        float2 ra = make_float2(acc[nf][0] + b0, acc[nf][1] + b1);
        float2 rb = make_float2(acc[nf][2] + b0, acc[nf][3] + b1);
        *(float2*)&g_feat[(size_t)rowa * C2 + col] = ra;
        *(float2*)&g_feat[(size_t)(rowa + 8) * C2 + col] = rb;
    }
}

// ---------------------------------------------------------------------------
// Normalize: rf = feat / max(||feat||, 1e-12); fp32 rf + fp16 hi/lo split.
// ---------------------------------------------------------------------------
__global__ void normalize_kernel() {
    const int n = blockIdx.x;
    const int c = threadIdx.x;
    float v = g_feat[(size_t)n * C2 + c];
    float s = v * v;
#pragma unroll
    for (int off = 16; off; off >>= 1) s += __shfl_xor_sync(0xffffffffu, s, off);
    __shared__ float ws[4];
    if ((c & 31) == 0) ws[c >> 5] = s;
    __syncthreads();
    float tot = ws[0] + ws[1] + ws[2] + ws[3];
    float norm = sqrtf(tot);
    float nf = v / fmaxf(norm, 1e-12f);
    g_rf[(size_t)n * C2 + c] = nf;
    __half hi = __float2half_rn(nf);
    g_hih[(size_t)n * C2 + c] = hi;
    g_loh[(size_t)n * C2 + c] = __float2half_rn(nf - __half2float(hi));
}

// ---------------------------------------------------------------------------
// Top-2 insert with jax top_k tie-breaking (equal value -> lower index).
// ---------------------------------------------------------------------------
__device__ __forceinline__ void ins2(float v, int j,
                                     float& v1, int& i1, float& v2, int& i2) {
    if (v > v1 || (v == v1 && j < i1)) {
        v2 = v1; i2 = i1; v1 = v; i1 = j;
    } else if (v > v2 || (v == v2 && j < i2)) {
        v2 = v; i2 = j;
    }
}

// ---------------------------------------------------------------------------
// Tensor-core (mma.sync fp16 3-term) similarity + top-2 (round-7 best config).
// Grid: (72 i-tiles, 2 j-halves, 2 batches) = 288 CTAs -> 2 CTAs/SM.
// ---------------------------------------------------------------------------
#define JT    64
#define JHALF (NB / JSPLIT)        // 4608
#define NTJ2  (JHALF / JT)         // 72
#define ALO_BYTES 32768            // A-lo resident: 128 rows x 256B
#define BUFB  32768                // one B buffer: hi 16KB + lo 16KB
#define SIM_SMEM (ALO_BYTES + 2 * BUFB)   // 96KB

__global__ void __launch_bounds__(256, 2) sim_mma_kernel() {
    extern __shared__ __align__(1024) char sm[];
    const int t = threadIdx.x;
    const int w = t >> 5, l = t & 31;
    const int jh = blockIdx.y;
    const int b  = blockIdx.z;
    const int i0 = blockIdx.x * 128;
    const int jbase = jh * JHALF;
    const __half* Hsrc = g_hih + (size_t)b * NB * C2;
    const __half* Lsrc = g_loh + (size_t)b * NB * C2;
    const uint32_t sbA = smem_u32(sm);          // A-lo resident region
    const uint32_t bb0 = sbA + ALO_BYTES;       // B buffers

    // ---- Stage A-lo (resident) + A-hi (temporarily in B region) ----
#pragma unroll
    for (int e = 0; e < 8; e++) {
        int id = e * 256 + t;          // 0..2047 : 128 rows x 16 chunks
        int r = id >> 4, c = id & 15;
        uint32_t o = sw_off(r, c);
        CP16(sbA + o, (const char*)(Lsrc + (size_t)(i0 + r) * C2) + c * 16);
        CP16(bb0 + o, (const char*)(Hsrc + (size_t)(i0 + r) * C2) + c * 16);
    }
    CPCOMMIT(); CPWAIT0();
    __syncthreads();

    // ---- A-hi fragments (register resident): a_hi[ks][4] ----
    const int sub = l >> 3;
    const int arl = ((sub & 1) << 3) + (l & 7);
    const int cb  = sub >> 1;
    const int ar  = w * 16 + arl;
    uint32_t a_hi[8][4];
#pragma unroll
    for (int ks = 0; ks < 8; ks++) {
        uint32_t ad = bb0 + sw_off(ar, ks * 2 + cb);
        LDSM4(a_hi[ks][0], a_hi[ks][1], a_hi[ks][2], a_hi[ks][3], ad);
    }
    __syncthreads();   // B region free for streaming now

    const int brn = ((sub >> 1) << 3) + (l & 7);
    const int bcb = sub & 1;

    // ---- prefetch B tile 0 into buffer 0 ----
#pragma unroll
    for (int e = 0; e < 4; e++) {
        int id = e * 256 + t;      // 0..1023 : 64 rows x 16 chunks
        int r = id >> 4, c = id & 15;
        uint32_t o = sw_off(r, c);
        CP16(bb0 + o,         (const char*)(Hsrc + (size_t)(jbase + r) * C2) + c * 16);
        CP16(bb0 + 16384 + o, (const char*)(Lsrc + (size_t)(jbase + r) * C2) + c * 16);
    }
    CPCOMMIT();

    float v1a = -INFINITY, v2a = -INFINITY, v1b = -INFINITY, v2b = -INFINITY;
    int   i1a = 0x7fffffff, i2a = 0x7fffffff, i1b = 0x7fffffff, i2b = 0x7fffffff;

    for (int jt = 0; jt < NTJ2; jt++) {
        CPWAIT0();
        __syncthreads();

        if (jt + 1 < NTJ2) {
            const int j0n = jbase + (jt + 1) * JT;
            const uint32_t bo = bb0 + (uint32_t)((jt + 1) & 1) * BUFB;
#pragma unroll
            for (int e = 0; e < 4; e++) {
                int id = e * 256 + t;
                int r = id >> 4, c = id & 15;
                uint32_t o = bo + sw_off(r, c);
                CP16(o,         (const char*)(Hsrc + (size_t)(j0n + r) * C2) + c * 16);
                CP16(o + 16384, (const char*)(Lsrc + (size_t)(j0n + r) * C2) + c * 16);
            }
            CPCOMMIT();
        }

        const uint32_t bo = bb0 + (uint32_t)(jt & 1) * BUFB;
        float acc[8][4];
#pragma unroll
        for (int nf = 0; nf < 8; nf++)
#pragma unroll
            for (int q = 0; q < 4; q++) acc[nf][q] = 0.f;

#pragma unroll
        for (int ks = 0; ks < 8; ks++) {
            const int ck = ks * 2;
            uint32_t al[4];
            LDSM4(al[0], al[1], al[2], al[3], sbA + sw_off(ar, ck + cb));
            uint32_t bf[16];
#pragma unroll
            for (int nb = 0; nb < 4; nb++) {
                uint32_t ad = bo + sw_off(nb * 16 + brn, ck + bcb);
                LDSM4(bf[4 * nb], bf[4 * nb + 1], bf[4 * nb + 2], bf[4 * nb + 3], ad);
            }
#pragma unroll
            for (int nf = 0; nf < 8; nf++) MMA16816(acc[nf], a_hi[ks], bf + 2 * nf);
#pragma unroll
            for (int nf = 0; nf < 8; nf++) MMA16816(acc[nf], al, bf + 2 * nf);
#pragma unroll
            for (int nb = 0; nb < 4; nb++) {
                uint32_t ad = bo + 16384 + sw_off(nb * 16 + brn, ck + bcb);
                LDSM4(bf[4 * nb], bf[4 * nb + 1], bf[4 * nb + 2], bf[4 * nb + 3], ad);
            }
#pragma unroll
            for (int nf = 0; nf < 8; nf++) MMA16816(acc[nf], a_hi[ks], bf + 2 * nf);
        }

        const int cbase = jbase + jt * JT + (l & 3) * 2;
        float mA = fmaxf(acc[0][0], acc[0][1]);
        float mB = fmaxf(acc[0][2], acc[0][3]);
#pragma unroll
        for (int nf = 1; nf < 8; nf++) {
            mA = fmaxf(mA, fmaxf(acc[nf][0], acc[nf][1]));
            mB = fmaxf(mB, fmaxf(acc[nf][2], acc[nf][3]));
        }
        if (mA >= v2a) {
#pragma unroll
            for (int nf = 0; nf < 8; nf++) {
                ins2(acc[nf][0], cbase + nf * 8,     v1a, i1a, v2a, i2a);
                ins2(acc[nf][1], cbase + nf * 8 + 1, v1a, i1a, v2a, i2a);
            }
        }
        if (mB >= v2b) {
#pragma unroll
            for (int nf = 0; nf < 8; nf++) {
                ins2(acc[nf][2], cbase + nf * 8,     v1b, i1b, v2b, i2b);
                ins2(acc[nf][3], cbase + nf * 8 + 1, v1b, i1b, v2b, i2b);
            }
        }
    }

#pragma unroll
    for (int off = 1; off <= 2; off <<= 1) {
        float ov1 = __shfl_xor_sync(0xffffffffu, v1a, off);
        int   oi1 = __shfl_xor_sync(0xffffffffu, i1a, off);
        float ov2 = __shfl_xor_sync(0xffffffffu, v2a, off);
        int   oi2 = __shfl_xor_sync(0xffffffffu, i2a, off);
        ins2(ov1, oi1, v1a, i1a, v2a, i2a);
        ins2(ov2, oi2, v1a, i1a, v2a, i2a);
        ov1 = __shfl_xor_sync(0xffffffffu, v1b, off);
        oi1 = __shfl_xor_sync(0xffffffffu, i1b, off);
        ov2 = __shfl_xor_sync(0xffffffffu, v2b, off);
        oi2 = __shfl_xor_sync(0xffffffffu, i2b, off);
        ins2(ov1, oi1, v1b, i1b, v2b, i2b);
        ins2(ov2, oi2, v1b, i1b, v2b, i2b);
    }
    if ((l & 3) == 0) {
        const int rowa = b * NB + i0 + w * 16 + (l >> 2);
        const int rowb = rowa + 8;
        const size_t pa = ((size_t)jh * NPIX + rowa) * 2;
        const size_t pb = ((size_t)jh * NPIX + rowb) * 2;
        g_t2v[pa]     = v1a; g_t2i[pa]     = i1a;
        g_t2v[pa + 1] = v2a; g_t2i[pa + 1] = i2a;
        g_t2v[pb]     = v1b; g_t2i[pb]     = i1b;
        g_t2v[pb + 1] = v2b; g_t2i[pb + 1] = i2b;
    }
}

// ---------------------------------------------------------------------------
// Merge j-halves + distance + mask (exact fp32 recompute, matches reference).
// ---------------------------------------------------------------------------
__global__ void dist_kernel(float* __restrict__ out) {
    const int gw   = (int)((blockIdx.x * blockDim.x + threadIdx.x) >> 5);
    const int lane = threadIdx.x & 31;
    if (gw >= NPIX) return;
    const int b = gw / NB;
    int nn = 0;
    if (lane == 0) {
        float v1 = -INFINITY, v2 = -INFINITY;
        int   i1 = 0x7fffffff, i2 = 0x7fffffff;
#pragma unroll
        for (int h = 0; h < JSPLIT; h++) {
            const size_t p = ((size_t)h * NPIX + gw) * 2;
            ins2(g_t2v[p],     g_t2i[p],     v1, i1, v2, i2);
            ins2(g_t2v[p + 1], g_t2i[p + 1], v1, i1, v2, i2);
        }
        nn = i2;
    }
    nn = __shfl_sync(0xffffffffu, nn, 0);
    const float* a = g_rf + (size_t)gw * C2;
    const float* c = g_rf + (size_t)(b * NB + nn) * C2;
    float4 av = *(const float4*)&a[lane * 4];
    float4 cv = *(const float4*)&c[lane * 4];
    float dx = av.x - cv.x, dy = av.y - cv.y, dz = av.z - cv.z, dw = av.w - cv.w;
    float s = dx * dx + dy * dy + dz * dz + dw * dw;
#pragma unroll
    for (int off = 16; off; off >>= 1) s += __shfl_xor_sync(0xffffffffu, s, off);
    if (lane == 0) {
        float d = sqrtf(s);
        out[NPIX + gw] = d;
        out[gw] = (d > MASK_THR) ? 1.0f : 0.0f;
    }
}

// ---------------------------------------------------------------------------
extern "C" void kernel_launch(void* const* d_in, const int* in_sizes, int n_in,
                              void* d_out, int out_size) {
    const float* features = (const float*)d_in[0];
    const float* W1 = (const float*)d_in[1];
    const float* b1 = (const float*)d_in[2];
    const float* W2 = (const float*)d_in[3];
    const float* b2 = (const float*)d_in[4];
    float* out = (float*)d_out;

    cudaFuncSetAttribute(sim_mma_kernel,
                         cudaFuncAttributeMaxDynamicSharedMemorySize, SIM_SMEM);
    cudaFuncSetAttribute(gemm1_mma_kernel,
                         cudaFuncAttributeMaxDynamicSharedMemorySize, MLP_SMEM);
    cudaFuncSetAttribute(gemm2_mma_kernel,
                         cudaFuncAttributeMaxDynamicSharedMemorySize, MLP_SMEM);

    splitw_kernel<<<(C1 * CIN + C2 * C1 + 255) / 256, 256>>>(W1, W2);
    transpose_split_kernel<<<dim3(NB / 32, CIN / 32, BATCH), dim3(32, 8)>>>(features);
    gemm1_mma_kernel<<<dim3(NPIX / 128, C1 / 64), 256, MLP_SMEM>>>(b1);
    gemm2_mma_kernel<<<dim3(NPIX / 128, C2 / 64), 256, MLP_SMEM>>>(b2);
    normalize_kernel<<<NPIX, 128>>>();
    sim_mma_kernel<<<dim3(NB / 128, JSPLIT, BATCH), 256, SIM_SMEM>>>();
    dist_kernel<<<(NPIX * 32 + 255) / 256, 256>>>(out);
}